// round 16
// baseline (speedup 1.0000x reference)
#include <cuda_runtime.h>
#include <cuda_bf16.h>
#include <cstdint>

#define BB 4
#define C 128
#define CO 256
#define H 128
#define W 128
#define HP 130
#define WP 130
#define HPWP (HP*WP)
#define KTOT 1152        // C*9, tap-major: k = n*128 + c

// ---------------- device scratch (static only, per harness rules) ----------
__device__ float g_xpad[BB*C*HP*WP];                 // padded input
__device__ float g_off[BB*H*W*2*9];                  // offsets [b][h][w][18]
__device__ __nv_bfloat16 g_wBhi[CO*KTOT];            // weights hi, [o][n*128+c]
__device__ __nv_bfloat16 g_wBlo[CO*KTOT];            // weights lo
__device__ float g_sums[2*CO];                       // BN partial sum / sumsq

// ---------------- PTX helpers ----------------------------------------------
__device__ __forceinline__ uint32_t smem_u32(const void* p) {
    uint32_t a;
    asm("{ .reg .u64 t; cvta.to.shared.u64 t, %1; cvt.u32.u64 %0, t; }" : "=r"(a) : "l"(p));
    return a;
}
__device__ __forceinline__ void mma_bf16(float* d, const uint32_t* a, const uint32_t* b) {
    asm volatile("mma.sync.aligned.m16n8k16.row.col.f32.bf16.bf16.f32 "
        "{%0,%1,%2,%3}, {%4,%5,%6,%7}, {%8,%9}, {%0,%1,%2,%3};"
        : "+f"(d[0]), "+f"(d[1]), "+f"(d[2]), "+f"(d[3])
        : "r"(a[0]), "r"(a[1]), "r"(a[2]), "r"(a[3]), "r"(b[0]), "r"(b[1]));
}
__device__ __forceinline__ void ldsm4(uint32_t* r, uint32_t addr) {
    asm volatile("ldmatrix.sync.aligned.m8n8.x4.shared.b16 {%0,%1,%2,%3}, [%4];"
        : "=r"(r[0]), "=r"(r[1]), "=r"(r[2]), "=r"(r[3]) : "r"(addr));
}
__device__ __forceinline__ void cp16(uint32_t dst, const void* src) {
    asm volatile("cp.async.cg.shared.global [%0], [%1], 16;" :: "r"(dst), "l"(src));
}
__device__ __forceinline__ uint32_t packbf(float lo, float hi) {
    uint32_t r;
    asm("cvt.rn.bf16x2.f32 %0, %1, %2;" : "=r"(r) : "f"(hi), "f"(lo));
    return r;
}
#define CP_COMMIT() asm volatile("cp.async.commit_group;" ::: "memory")
#define CP_WAIT2()  asm volatile("cp.async.wait_group 2;" ::: "memory")
#define MBAR_INIT(a, cnt) asm volatile("mbarrier.init.shared.b64 [%0], %1;" :: "r"(a), "r"(cnt) : "memory")
#define BAR_CONS()  asm volatile("bar.sync 1, 256;" ::: "memory")

__device__ __forceinline__ void mbar_arrive(uint32_t a) {
    unsigned long long st;
    asm volatile("mbarrier.arrive.release.cta.shared::cta.b64 %0, [%1];"
                 : "=l"(st) : "r"(a) : "memory");
}
__device__ __forceinline__ void mbar_wait(uint32_t mbar, uint32_t parity) {
    uint32_t done;
    asm volatile("{\n .reg .pred p;\n mbarrier.try_wait.parity.acquire.cta.shared::cta.b64 p, [%1], %2;\n selp.b32 %0,1,0,p;\n}"
                 : "=r"(done) : "r"(mbar), "r"(parity) : "memory");
    if (!done) {
        asm volatile("{\n .reg .pred P1;\nWL_%=:\n mbarrier.try_wait.parity.acquire.cta.shared::cta.b64 P1, [%0], %1, 0x989680;\n @P1 bra.uni WD_%=;\n bra.uni WL_%=;\nWD_%=:\n}"
                     :: "r"(mbar), "r"(parity) : "memory");
    }
}

// ---------------------------------------------------------------------------
__global__ void pad_kernel(const float* __restrict__ x) {
    int idx = blockIdx.x*blockDim.x + threadIdx.x;
    if (idx < 2*CO) g_sums[idx] = 0.f;               // zero BN accumulators
    if (idx >= BB*C*HP*WP) return;
    int j = idx % WP; int t = idx / WP; int i = t % HP; int bc = t / HP;
    float v = 0.f;
    if (i >= 1 && i <= H && j >= 1 && j <= W)
        v = x[(bc*H + (i-1))*W + (j-1)];
    g_xpad[idx] = v;
}

// split weights to bf16 hi/lo, reorder to tap-major k = n*128 + c
__global__ void wprep_kernel(const float* __restrict__ w) {
    int idx = blockIdx.x*blockDim.x + threadIdx.x;
    if (idx >= CO*KTOT) return;
    int o = idx / KTOT, r = idx % KTOT;
    int n = r >> 7, c = r & 127;
    float v = w[(o*C + c)*9 + n];
    __nv_bfloat16 hi = __float2bfloat16(v);
    __nv_bfloat16 lo = __float2bfloat16(v - __bfloat162float(hi));
    g_wBhi[idx] = hi;
    g_wBlo[idx] = lo;
}

// ---------------------------------------------------------------------------
// Offset conv: 18 out channels, 3x3, pad 1. One thread per (b,h,w). (R6 version)
__global__ __launch_bounds__(128) void offconv_kernel(
        const float* __restrict__ pw, const float* __restrict__ pb) {
    __shared__ float s_pw[576*20];
    int b = blockIdx.x / H, h = blockIdx.x % H;
    int w = threadIdx.x;
    float acc[18];
    #pragma unroll
    for (int j = 0; j < 18; j++) acc[j] = pb[j];

    for (int cc = 0; cc < 2; cc++) {
        __syncthreads();
        for (int i = threadIdx.x; i < 576*18; i += 128) {
            int k = i / 18, j = i - (i/18)*18;
            s_pw[k*20 + j] = pw[j*KTOT + cc*576 + k];
        }
        __syncthreads();
        for (int k = 0; k < 576; k++) {
            int c = cc*64 + k/9;
            int kidx = k - (k/9)*9;
            float xv = g_xpad[((b*C + c)*HP + h + kidx/3)*WP + w + kidx%3];
            const float4* r = (const float4*)(s_pw + k*20);
            float4 a0 = r[0], a1 = r[1], a2 = r[2], a3 = r[3];
            float b0 = s_pw[k*20+16], b1 = s_pw[k*20+17];
            acc[0]  += xv*a0.x; acc[1]  += xv*a0.y; acc[2]  += xv*a0.z; acc[3]  += xv*a0.w;
            acc[4]  += xv*a1.x; acc[5]  += xv*a1.y; acc[6]  += xv*a1.z; acc[7]  += xv*a1.w;
            acc[8]  += xv*a2.x; acc[9]  += xv*a2.y; acc[10] += xv*a2.z; acc[11] += xv*a2.w;
            acc[12] += xv*a3.x; acc[13] += xv*a3.y; acc[14] += xv*a3.z; acc[15] += xv*a3.w;
            acc[16] += xv*b0;   acc[17] += xv*b1;
        }
    }
    float* op = g_off + (((b*H + h)*W) + w)*18;
    #pragma unroll
    for (int j = 0; j < 18; j++) op[j] = acc[j];
}

// ---------------------------------------------------------------------------
// Warp-specialized deformable implicit GEMM (bf16 hi/lo split, 3 products).
// Producers (warps 0-7): gather A only, software-pipelined LDGs.
// Consumers (warps 8-15): self-feed B via cp.async (NST ahead), ldsm + mma.
// Tile M=64 x N=256, K=1152 in 72 half-chunks; 3-stage mbarrier ring for A.
#define NHC 72
#define NST 3
#define ARS 48
#define S_AH 0
#define S_AL 3072
#define S_BH 6144
#define S_BL 18432
#define STG  30720
#define SMEM_DYN (NST*STG)

__global__ __launch_bounds__(512, 1) void deform_mma(float* __restrict__ out) {
    extern __shared__ char sm[];
    __shared__ alignas(8) unsigned long long s_mbar[2*NST];   // full[0..2], empty[3..5]

    const int tid  = threadIdx.x;
    const int lane = tid & 31;
    const int wid  = tid >> 5;       // 0..15
    const int b    = blockIdx.y;
    const int h    = blockIdx.x >> 1;
    const int w0   = (blockIdx.x & 1) * 64;
    const uint32_t sbase = smem_u32(sm);
    const uint32_t mb = smem_u32(&s_mbar[0]);

    if (tid == 0) {
        #pragma unroll
        for (int s = 0; s < NST; s++) {
            MBAR_INIT(mb + s*8, 256);            // full[s]: 256 producer threads
            MBAR_INIT(mb + (NST+s)*8, 256);      // empty[s]: 256 consumer threads
        }
    }
    __syncthreads();

    float acc[2][8][4];
    #pragma unroll
    for (int mi = 0; mi < 2; mi++)
        #pragma unroll
        for (int nt = 0; nt < 8; nt++)
            #pragma unroll
            for (int j = 0; j < 4; j++) acc[mi][nt][j] = 0.f;

    if (wid < 8) {
        // ================= PRODUCER (A gather only) =================
        const int pos = (wid & 1)*32 + lane;     // gather position (0..63)
        const int cg  = wid >> 1;                // gather channel group (4 ch)
        int i00 = 0, i01 = 0, i10 = 0, i11 = 0;
        float gg0 = 0.f, gg1 = 0.f, gg2 = 0.f, gg3 = 0.f;
        float raw[16];

        auto calc_params = [&](int n) {
            const float* offp = g_off + ((size_t)((b*H + h)*W + w0 + pos))*18;
            float ox = offp[n], oy = offp[9 + n];
            float px = (float)(h + n/3) + ox;
            float py = (float)(w0 + pos + n%3) + oy;
            float fx = floorf(px), fy = floorf(py);
            float x0 = fminf(fmaxf(fx,     0.f), 129.f);
            float x1 = fminf(fmaxf(fx+1.f, 0.f), 129.f);
            float y0 = fminf(fmaxf(fy,     0.f), 129.f);
            float y1 = fminf(fmaxf(fy+1.f, 0.f), 129.f);
            float pcx = fminf(fmaxf(px, 0.f), 129.f);
            float pcy = fminf(fmaxf(py, 0.f), 129.f);
            float wx0 = 1.f + (x0 - pcx), wx1 = 1.f - (x1 - pcx);
            float wy0 = 1.f + (y0 - pcy), wy1 = 1.f - (y1 - pcy);
            int ix0 = (int)x0 * WP, ix1 = (int)x1 * WP;
            int iy0 = (int)y0,      iy1 = (int)y1;
            i00 = ix0 + iy0; i01 = ix0 + iy1; i10 = ix1 + iy0; i11 = ix1 + iy1;
            gg0 = wx0*wy0; gg1 = wx1*wy1; gg2 = wx0*wy1; gg3 = wx1*wy0;
        };
        auto prefetch = [&](int ii) {
            int ch = (ii & 7) * 16 + cg*4;
            const float* __restrict__ base = g_xpad + ((size_t)(b*C + ch))*HPWP;
            #pragma unroll
            for (int cc = 0; cc < 4; cc++) {
                const float* __restrict__ Xp = base + (size_t)cc*HPWP;
                raw[cc*4+0] = Xp[i00];
                raw[cc*4+1] = Xp[i11];
                raw[cc*4+2] = Xp[i01];
                raw[cc*4+3] = Xp[i10];
            }
        };

        calc_params(0);
        prefetch(0);

        int s = 0, wrap = 0;
        for (int i = 0; i < NHC; i++) {
            if (i >= NST) mbar_wait(mb + (NST+s)*8, (wrap-1) & 1);

            // combine + convert + store A(i)
            {
                char* st = sm + s*STG;
                float v0 = gg0*raw[0]  + gg1*raw[1]  + gg2*raw[2]  + gg3*raw[3];
                float v1 = gg0*raw[4]  + gg1*raw[5]  + gg2*raw[6]  + gg3*raw[7];
                float v2 = gg0*raw[8]  + gg1*raw[9]  + gg2*raw[10] + gg3*raw[11];
                float v3 = gg0*raw[12] + gg1*raw[13] + gg2*raw[14] + gg3*raw[15];
                uint32_t hp0 = packbf(v0, v1);
                uint32_t hp1 = packbf(v2, v3);
                float l0 = v0 - __uint_as_float(hp0 << 16);
                float l1 = v1 - __uint_as_float(hp0 & 0xFFFF0000u);
                float l2 = v2 - __uint_as_float(hp1 << 16);
                float l3 = v3 - __uint_as_float(hp1 & 0xFFFF0000u);
                uint32_t lp0 = packbf(l0, l1);
                uint32_t lp1 = packbf(l2, l3);
                *(uint2*)(st + S_AH + pos*ARS + cg*8) = make_uint2(hp0, hp1);
                *(uint2*)(st + S_AL + pos*ARS + cg*8) = make_uint2(lp0, lp1);
            }
            mbar_arrive(mb + s*8);               // full[s], release (orders STS)

            if (i + 1 < NHC) {                   // pipeline next gather
                if (((i+1) & 7) == 0) calc_params((i+1) >> 3);
                prefetch(i + 1);
            }
            if (++s == NST) { s = 0; wrap++; }
        }
    } else {
        // ================= CONSUMER (B feed + MMA) =================
        const int cw = wid - 8;
        const int wm = cw & 1;
        const int wn = cw >> 1;
        const int ob = tid & 255;                // B row owned by this thread
        const uint32_t aoff = (uint32_t)((wm*32 + (lane & 7) + ((lane >> 3) & 1)*8)*ARS + (lane >> 4)*16);
        const uint32_t boff = (uint32_t)((wn*64 + (lane & 7) + (lane >> 4)*8)*ARS + ((lane >> 3) & 1)*16);

        auto issue_B = [&](int hn) {
            if (hn < NHC) {
                uint32_t stu = sbase + (hn % NST)*STG;
                int n = hn >> 3, ch = (hn & 7)*16;
                size_t srcoff = (size_t)ob*KTOT + n*128 + ch;
                cp16(stu + S_BH + ob*ARS,      g_wBhi + srcoff);
                cp16(stu + S_BH + ob*ARS + 16, g_wBhi + srcoff + 8);
                cp16(stu + S_BL + ob*ARS,      g_wBlo + srcoff);
                cp16(stu + S_BL + ob*ARS + 16, g_wBlo + srcoff + 8);
            }
            CP_COMMIT();                         // empty group in tail keeps count
        };

        #pragma unroll
        for (int k = 0; k < NST; k++) issue_B(k);

        int s = 0, wrap = 0;
        for (int i = 0; i < NHC; i++) {
            mbar_wait(mb + s*8, wrap & 1);       // A(i) ready (acquire)
            CP_WAIT2();                          // own B(i) stripes landed
            BAR_CONS();                          // all consumers' stripes visible
            const uint32_t stu = sbase + s*STG;

            uint32_t ah[2][4], al[2][4];
            ldsm4(ah[0], stu + S_AH + aoff);
            ldsm4(ah[1], stu + S_AH + aoff + 16*ARS);
            ldsm4(al[0], stu + S_AL + aoff);
            ldsm4(al[1], stu + S_AL + aoff + 16*ARS);
            #pragma unroll
            for (int j = 0; j < 4; j++) {
                uint32_t bh[4], bl[4];
                ldsm4(bh, stu + S_BH + boff + j*16*ARS);
                ldsm4(bl, stu + S_BL + boff + j*16*ARS);
                #pragma unroll
                for (int mi = 0; mi < 2; mi++) {
                    mma_bf16(acc[mi][2*j],   ah[mi], bh);
                    mma_bf16(acc[mi][2*j],   ah[mi], bl);
                    mma_bf16(acc[mi][2*j],   al[mi], bh);
                    mma_bf16(acc[mi][2*j+1], ah[mi], bh + 2);
                    mma_bf16(acc[mi][2*j+1], ah[mi], bl + 2);
                    mma_bf16(acc[mi][2*j+1], al[mi], bh + 2);
                }
            }

            mbar_arrive(mb + (NST+s)*8);         // empty[s] (A reads done)
            BAR_CONS();                          // all consumers done reading B[s]
            issue_B(i + NST);                    // refill the stage just drained
            if (++s == NST) { s = 0; wrap++; }
        }
    }

    __syncthreads();

    // ---- epilogue: transpose via smem; fused BN partial sums ----
    float* sepi = (float*)sm;        // [64 ch][65 pos] fp32 = 16.6 KB
    const int r  = lane >> 2;
    const int tq = lane & 3;
    const int cw = wid - 8;
    for (int qt = 0; qt < 4; qt++) {
        if (wid >= 8 && (cw >> 1) == qt) {
            const int wm = cw & 1;
            #pragma unroll
            for (int mi = 0; mi < 2; mi++) {
                int pos0 = wm*32 + mi*16 + r;
                #pragma unroll
                for (int nt = 0; nt < 8; nt++) {
                    int ch0 = nt*8 + tq*2;
                    sepi[(ch0  )*65 + pos0    ] = acc[mi][nt][0];
                    sepi[(ch0+1)*65 + pos0    ] = acc[mi][nt][1];
                    sepi[(ch0  )*65 + pos0 + 8] = acc[mi][nt][2];
                    sepi[(ch0+1)*65 + pos0 + 8] = acc[mi][nt][3];
                }
            }
        }
        __syncthreads();
        {
            int ri = tid >> 3, j = tid & 7;          // 64 rows x 8 segs of 8
            int o = qt*64 + ri;
            const float* src = sepi + ri*65 + j*8;
            float* dst = out + (((size_t)b*CO + o)*H + h)*W + w0 + j*8;
            float s1 = 0.f, s2 = 0.f;
            #pragma unroll
            for (int k4 = 0; k4 < 2; k4++) {
                float4 v = make_float4(src[k4*4+0], src[k4*4+1], src[k4*4+2], src[k4*4+3]);
                *(float4*)(dst + k4*4) = v;
                s1 += v.x + v.y + v.z + v.w;
                s2 += v.x*v.x + v.y*v.y + v.z*v.z + v.w*v.w;
            }
            #pragma unroll
            for (int m = 1; m < 8; m <<= 1) {
                s1 += __shfl_xor_sync(0xffffffffu, s1, m);
                s2 += __shfl_xor_sync(0xffffffffu, s2, m);
            }
            if (j == 0) {
                atomicAdd(&g_sums[o], s1);
                atomicAdd(&g_sums[CO + o], s2);
            }
        }
        __syncthreads();
    }
}

// ---------------------------------------------------------------------------
__global__ void bn_apply(float* __restrict__ out,
                         const float* __restrict__ gamma,
                         const float* __restrict__ beta) {
    int idx = blockIdx.x*blockDim.x + threadIdx.x;
    const int total4 = BB*CO*H*W/4;
    if (idx >= total4) return;
    int o = ((idx*4) / (H*W)) % CO;
    const float inv = 1.f / (float)(BB*H*W);
    float mean = g_sums[o] * inv;
    float var  = g_sums[CO + o] * inv - mean*mean;
    float sc = gamma[o] * rsqrtf(var + 1e-5f);
    float sh = beta[o] - mean*sc;
    float4 v = ((float4*)out)[idx];
    v.x = v.x*sc + sh; v.x = v.x >= 0.f ? v.x : 0.1f*v.x;
    v.y = v.y*sc + sh; v.y = v.y >= 0.f ? v.y : 0.1f*v.y;
    v.z = v.z*sc + sh; v.z = v.z >= 0.f ? v.z : 0.1f*v.z;
    v.w = v.w*sc + sh; v.w = v.w >= 0.f ? v.w : 0.1f*v.w;
    ((float4*)out)[idx] = v;
}

// ---------------------------------------------------------------------------
extern "C" void kernel_launch(void* const* d_in, const int* in_sizes, int n_in,
                              void* d_out, int out_size) {
    const float* x      = (const float*)d_in[0];
    const float* p_w    = (const float*)d_in[1];
    const float* p_b    = (const float*)d_in[2];
    const float* w_conv = (const float*)d_in[3];
    const float* gamma  = (const float*)d_in[4];
    const float* beta   = (const float*)d_in[5];
    float* out = (float*)d_out;

    cudaFuncSetAttribute(deform_mma, cudaFuncAttributeMaxDynamicSharedMemorySize, SMEM_DYN);

    pad_kernel    <<<(BB*C*HP*WP + 255)/256, 256>>>(x);
    wprep_kernel  <<<(CO*KTOT + 255)/256, 256>>>(w_conv);
    offconv_kernel<<<BB*H, 128>>>(p_w, p_b);
    deform_mma    <<<dim3(H*2, BB), 512, SMEM_DYN>>>(out);
    bn_apply      <<<(BB*CO*H*W/4 + 255)/256, 256>>>(out, gamma, beta);
}